// round 5
// baseline (speedup 1.0000x reference)
#include <cuda_runtime.h>
#include <math.h>

#define NN 20000
#define NE 640000
#define DD 128
#define OUTD 256
#define BBATCH 64
#define HOUT 62
#define MPI (HOUT*HOUT)   // 3844 pixels per image
#define MT 31             // M-tiles of 128 per image (31*128 = 3968 >= 3844)
#define KTOT 1152

// ---------------- scratch (device globals; no allocation allowed) ----------------
__device__ __align__(16) float g_inv_sigma[4];
__device__ __align__(16) float g_wT[KTOT * DD];        // conv weights [k][co], /sigma
__device__ __align__(16) float g_fcvT[512 * OUTD];     // fcv_w transposed, /sigma
__device__ __align__(16) float g_fctT[DD * OUTD];      // fct_w transposed, /sigma
__device__ __align__(16) float g_partial[BBATCH * MT * 4 * DD];
__device__ __align__(16) float g_pool_vis[BBATCH * DD * 4];
__device__ __align__(16) float g_topo_part[BBATCH * 4 * DD];
__device__ __align__(16) float g_deg[NN];
__device__ __align__(16) float g_dis[NN];
__device__ __align__(16) float g_xw[NN * DD];
__device__ __align__(16) float g_h[NN * DD];

__device__ __forceinline__ int clampi(int v, int lo, int hi) {
    return v < lo ? lo : (v > hi ? hi : v);
}

__device__ __forceinline__ float block_reduce_sum(float v, float* red) {
    int tid = threadIdx.x;
    red[tid] = v;
    __syncthreads();
    for (int s = 128; s > 0; s >>= 1) {
        if (tid < s) red[tid] += red[tid + s];
        __syncthreads();
    }
    float r = red[0];
    __syncthreads();
    return r;
}

// ---------------- spectral norm sigma (one launch per matrix) --------------------
__global__ void sigma_kernel(const float* W, const float* u, int R, int C, int slot) {
    __shared__ float sv[1152];
    __shared__ float red[256];
    int tid = threadIdx.x;

    float ss = 0.f;
    for (int j = tid; j < C; j += 256) {
        float t = 0.f;
        for (int i = 0; i < R; i++) t += W[i * C + j] * u[i];
        sv[j] = t;
        ss += t * t;
    }
    __syncthreads();
    float nrm2 = block_reduce_sum(ss, red);
    float invn = 1.0f / (sqrtf(nrm2) + 1e-12f);

    float ss2 = 0.f;
    for (int i = tid; i < R; i += 256) {
        float s = 0.f;
        for (int j = 0; j < C; j++) s += W[i * C + j] * sv[j];
        s *= invn;
        ss2 += s * s;
    }
    float sig2 = block_reduce_sum(ss2, red);
    if (tid == 0) {
        float sigma = sig2 / (sqrtf(sig2) + 1e-12f);
        g_inv_sigma[slot] = 1.0f / sigma;
    }
}

// ---------------- transpose + scale weights (separate kernels, no ptr select) ----
__global__ void transpose_w(const float* src) {   // [128,1152] -> g_wT [1152,128]
    int idx = blockIdx.x * 256 + threadIdx.x;
    if (idx >= 128 * 1152) return;
    int r = idx / 1152, c = idx - r * 1152;
    g_wT[c * 128 + r] = src[idx] * g_inv_sigma[0];
}
__global__ void transpose_fcv(const float* src) { // [256,512] -> g_fcvT [512,256]
    int idx = blockIdx.x * 256 + threadIdx.x;
    if (idx >= 256 * 512) return;
    int r = idx / 512, c = idx - r * 512;
    g_fcvT[c * 256 + r] = src[idx] * g_inv_sigma[1];
}
__global__ void transpose_fct(const float* src) { // [256,128] -> g_fctT [128,256]
    int idx = blockIdx.x * 256 + threadIdx.x;
    if (idx >= 256 * 128) return;
    int r = idx / 128, c = idx - r * 128;
    g_fctT[c * 256 + r] = src[idx] * g_inv_sigma[2];
}

// ---------------- init scratch ----------------
__global__ void init_kernel() {
    int idx = blockIdx.x * 256 + threadIdx.x;
    if (idx < NN * DD) g_h[idx] = 0.f;
    if (idx < NN) g_deg[idx] = 1.0f;  // self loop
}

// ---------------- degree + normalization ----------------
__global__ void deg_kernel(const int* __restrict__ ei) {
    int e = blockIdx.x * 256 + threadIdx.x;
    if (e < NE) {
        int dst = clampi(ei[NE + e], 0, NN - 1);
        atomicAdd(&g_deg[dst], 1.0f);
    }
}
__global__ void dis_kernel() {
    int i = blockIdx.x * 256 + threadIdx.x;
    if (i < NN) g_dis[i] = rsqrtf(g_deg[i]);
}

// ---------------- xw = topo @ gcn_w ----------------
__global__ void xw_kernel(const float* __restrict__ topo, const float* __restrict__ gw) {
    __shared__ float st[8 * 128];
    int n0 = blockIdx.x * 8;
    int tid = threadIdx.x;  // 128 threads
#pragma unroll
    for (int i = 0; i < 8; i++) st[i * 128 + tid] = topo[(n0 + i) * 128 + tid];
    __syncthreads();
    float acc[8];
#pragma unroll
    for (int r = 0; r < 8; r++) acc[r] = 0.f;
    for (int k = 0; k < 128; k++) {
        float w = gw[k * 128 + tid];
#pragma unroll
        for (int r = 0; r < 8; r++) acc[r] += st[r * 128 + k] * w;
    }
#pragma unroll
    for (int r = 0; r < 8; r++) g_xw[(n0 + r) * 128 + tid] = acc[r];
}

// ---------------- edge scatter: h[dst] += dis[src]*dis[dst] * xw[src] -------------
__global__ void scatter_kernel(const int* __restrict__ ei) {
    int e = blockIdx.x * 8 + (threadIdx.x >> 5);
    if (e >= NE) return;
    int lane = threadIdx.x & 31;
    int src = clampi(ei[e], 0, NN - 1);
    int dst = clampi(ei[NE + e], 0, NN - 1);
    float nrm = g_dis[src] * g_dis[dst];
#pragma unroll
    for (int q = 0; q < 4; q++) {
        int c = lane + q * 32;
        atomicAdd(&g_h[dst * 128 + c], g_xw[src * 128 + c] * nrm);
    }
}

// ---------------- topo pool: per-graph binary search, striped, NO atomics ---------
__global__ void topo_pool_kernel(const int* __restrict__ batch,
                                 const float* __restrict__ gb) {
    int b = blockIdx.x;          // graph id
    int stripe = blockIdx.y;     // 0..3
    int c = threadIdx.x;         // channel 0..127

    int lo = 0, hi = NN;
    while (lo < hi) { int mid = (lo + hi) >> 1; if (batch[mid] < b) lo = mid + 1; else hi = mid; }
    int s = lo;
    lo = s; hi = NN;
    while (lo < hi) { int mid = (lo + hi) >> 1; if (batch[mid] < b + 1) lo = mid + 1; else hi = mid; }
    int e = lo;

    float bias = gb[c];
    float m = -INFINITY;
    for (int n = s + stripe; n < e; n += 4) {
        float d = g_dis[n];
        float val = g_h[n * 128 + c] + d * d * g_xw[n * 128 + c] + bias;
        val = (val >= 0.f) ? val : 0.2f * val;
        m = fmaxf(m, val);
    }
    g_topo_part[(b * 4 + stripe) * 128 + c] = m;
}

// ---------------- conv3x3 (implicit GEMM) + leaky + fused 2x2 adaptive maxpool ----
__global__ void __launch_bounds__(256, 2)
conv_kernel(const float* __restrict__ vis, const float* __restrict__ cb) {
    __shared__ float smem[8192];
    float* sA = smem;
    float* sB = smem + 1024;

    int tid = threadIdx.x;
    int img = blockIdx.x / MT;
    int mt = blockIdx.x - img * MT;
    int m0 = mt * 128;

    int p = tid & 127;   // pixel within tile (A) / c_out (B)
    int kb = tid >> 7;   // 0/1
    int s = m0 + p;
    bool valid = (s < MPI);
    int y = s / HOUT;
    int x = s - y * HOUT;
    const float* base = vis + ((long)(img * 128) * 64 + y) * 64 + x;

    int ty = tid >> 4, tx = tid & 15;

    float acc[8][8];
#pragma unroll
    for (int i = 0; i < 8; i++)
#pragma unroll
        for (int j = 0; j < 8; j++) acc[i][j] = 0.f;

    for (int k0 = 0; k0 < KTOT; k0 += 8) {
#pragma unroll
        for (int i = 0; i < 4; i++) {
            int k = kb + 2 * i;
            int kg = k0 + k;
            int ci = kg / 9;
            int rem = kg - ci * 9;
            int ky = rem / 3;
            int kx = rem - ky * 3;
            float v = 0.f;
            if (valid) v = base[ci * 4096 + ky * 64 + kx];
            sA[k * 128 + p] = v;
            sB[k * 128 + p] = g_wT[kg * 128 + p];
        }
        __syncthreads();
#pragma unroll
        for (int kk = 0; kk < 8; kk++) {
            float a[8], b[8];
#pragma unroll
            for (int i = 0; i < 8; i++) a[i] = sA[kk * 128 + ty * 8 + i];
#pragma unroll
            for (int j = 0; j < 8; j++) b[j] = sB[kk * 128 + tx * 8 + j];
#pragma unroll
            for (int i = 0; i < 8; i++)
#pragma unroll
                for (int j = 0; j < 8; j++) acc[i][j] += a[i] * b[j];
        }
        __syncthreads();
    }

    // epilogue: bias + leaky, per-thread per-region max (registers)
    float rmax[4][8];
#pragma unroll
    for (int r = 0; r < 4; r++)
#pragma unroll
        for (int j = 0; j < 8; j++) rmax[r][j] = -INFINITY;

#pragma unroll
    for (int i = 0; i < 8; i++) {
        int ss = m0 + ty * 8 + i;
        if (ss < MPI) {
            int yy = ss / HOUT;
            int xx = ss - yy * HOUT;
            int reg = ((yy >= 31) ? 2 : 0) + ((xx >= 31) ? 1 : 0);
#pragma unroll
            for (int j = 0; j < 8; j++) {
                float v = acc[i][j] + cb[tx * 8 + j];
                v = (v >= 0.f) ? v : 0.2f * v;
                rmax[reg][j] = fmaxf(rmax[reg][j], v);
            }
        }
    }

    __syncthreads();
#pragma unroll
    for (int r = 0; r < 4; r++)
#pragma unroll
        for (int j = 0; j < 8; j++)
            smem[(ty * 4 + r) * 128 + tx * 8 + j] = rmax[r][j];
    __syncthreads();

    for (int o = tid; o < 512; o += 256) {
        int r = o >> 7;
        int col = o & 127;
        float m = -INFINITY;
#pragma unroll
        for (int t2 = 0; t2 < 16; t2++) m = fmaxf(m, smem[(t2 * 4 + r) * 128 + col]);
        g_partial[((img * MT + mt) * 4 + r) * 128 + col] = m;
    }
}

// ---------------- reduce conv-tile partials -> g_pool_vis ----------------
__global__ void vis_reduce_kernel() {
    int img = blockIdx.x;
    int o = threadIdx.x;        // 512: (reg, col)
    int r = o >> 7;
    int col = o & 127;
    float m = -INFINITY;
    for (int mt = 0; mt < MT; mt++)
        m = fmaxf(m, g_partial[((img * MT + mt) * 4 + r) * 128 + col]);
    g_pool_vis[img * 512 + col * 4 + r] = m;   // (C,2,2) flatten -> col*4 + reg
}

// ---------------- vis score: [64,512] @ fcvT[512,256] + b ----------------
__global__ void vis_score_kernel(const float* __restrict__ fcvb, float* __restrict__ out) {
    __shared__ float xs[512];
    int b = blockIdx.x, tid = threadIdx.x;
    for (int i = tid; i < 512; i += 256) xs[i] = g_pool_vis[b * 512 + i];
    __syncthreads();
    float acc = fcvb[tid];
    for (int j = 0; j < 512; j++) acc += xs[j] * g_fcvT[j * OUTD + tid];
    out[b * OUTD + tid] = acc;
}

// ---------------- topo score: fold stripes -> [64,128] @ fctT + b ----------------
__global__ void topo_score_kernel(const float* __restrict__ fctb, float* __restrict__ out) {
    __shared__ float xs[128];
    int b = blockIdx.x, tid = threadIdx.x;
    if (tid < 128) {
        float m = g_topo_part[(b * 4 + 0) * 128 + tid];
        m = fmaxf(m, g_topo_part[(b * 4 + 1) * 128 + tid]);
        m = fmaxf(m, g_topo_part[(b * 4 + 2) * 128 + tid]);
        m = fmaxf(m, g_topo_part[(b * 4 + 3) * 128 + tid]);
        xs[tid] = m;
    }
    __syncthreads();
    float acc = fctb[tid];
    for (int j = 0; j < 128; j++) acc += xs[j] * g_fctT[j * OUTD + tid];
    out[BBATCH * OUTD + b * OUTD + tid] = acc;
}

// ---------------- launch ----------------
extern "C" void kernel_launch(void* const* d_in, const int* in_sizes, int n_in,
                              void* d_out, int out_size) {
    const float* vis    = (const float*)d_in[0];
    const float* topo   = (const float*)d_in[1];
    const int*   ei     = (const int*)d_in[2];     // int64 in reference -> int32 in harness
    const int*   batch  = (const int*)d_in[3];     // int64 in reference -> int32 in harness
    const float* conv_w = (const float*)d_in[4];
    const float* conv_b = (const float*)d_in[5];
    const float* conv_u = (const float*)d_in[6];
    const float* fcv_w  = (const float*)d_in[7];
    const float* fcv_b  = (const float*)d_in[8];
    const float* fcv_u  = (const float*)d_in[9];
    const float* gcn_w  = (const float*)d_in[10];
    const float* gcn_b  = (const float*)d_in[11];
    const float* fct_w  = (const float*)d_in[12];
    const float* fct_b  = (const float*)d_in[13];
    const float* fct_u  = (const float*)d_in[14];
    float*       out    = (float*)d_out;

    sigma_kernel<<<1, 256>>>(conv_w, conv_u, 128, 1152, 0);
    sigma_kernel<<<1, 256>>>(fcv_w, fcv_u, 256, 512, 1);
    sigma_kernel<<<1, 256>>>(fct_w, fct_u, 256, 128, 2);

    transpose_w  <<<(128 * 1152 + 255) / 256, 256>>>(conv_w);
    transpose_fcv<<<(256 * 512 + 255) / 256, 256>>>(fcv_w);
    transpose_fct<<<(256 * 128 + 255) / 256, 256>>>(fct_w);

    init_kernel<<<(NN * DD + 255) / 256, 256>>>();

    // vision head (dominant)
    conv_kernel<<<BBATCH * MT, 256>>>(vis, conv_b);
    vis_reduce_kernel<<<BBATCH, 512>>>();

    // topo head
    deg_kernel<<<(NE + 255) / 256, 256>>>(ei);
    dis_kernel<<<(NN + 255) / 256, 256>>>();
    xw_kernel<<<NN / 8, 128>>>(topo, gcn_w);
    scatter_kernel<<<NE / 8, 256>>>(ei);
    {
        dim3 g(BBATCH, 4);
        topo_pool_kernel<<<g, 128>>>(batch, gcn_b);
    }

    // heads
    vis_score_kernel<<<BBATCH, 256>>>(fcv_b, out);
    topo_score_kernel<<<BBATCH, 256>>>(fct_b, out);
}

// round 7
// speedup vs baseline: 1.0825x; 1.0825x over previous
#include <cuda_runtime.h>
#include <math.h>
#include <stdint.h>

#define NN 20000
#define NE 640000
#define DD 128
#define OUTD 256
#define BBATCH 64
#define HOUT 62
#define MPI (HOUT*HOUT)   // 3844 pixels per image
#define MT 31             // M-tiles of 128 per image
#define KTOT 1152
#define KC 32             // K chunk
#define NCHUNK (KTOT/KC)  // 36

// ---------------- scratch ----------------
__device__ __align__(16) float g_inv_sigma[4];
__device__ __align__(16) float g_ws[DD * KTOT];        // conv weights [cout][k]/sigma, tf32-rounded
__device__ __align__(16) float g_fcvT[512 * OUTD];
__device__ __align__(16) float g_fctT[DD * OUTD];
__device__ __align__(16) float g_partial[BBATCH * MT * 4 * DD];
__device__ __align__(16) float g_pool_vis[BBATCH * DD * 4];
__device__ __align__(16) float g_topo_part[BBATCH * 4 * DD];
__device__ __align__(16) float g_deg[NN];
__device__ __align__(16) float g_dis[NN];
__device__ __align__(16) float g_xw[NN * DD];
__device__ __align__(16) float g_h[NN * DD];

__device__ __forceinline__ int clampi(int v, int lo, int hi) {
    return v < lo ? lo : (v > hi ? hi : v);
}
__device__ __forceinline__ uint32_t f2tf32(float f) {
    uint32_t u;
    asm("cvt.rna.tf32.f32 %0, %1;" : "=r"(u) : "f"(f));
    return u;
}
__device__ __forceinline__ void mma_tf32(float* d, const uint32_t* a, const uint32_t* b) {
    asm volatile(
        "mma.sync.aligned.m16n8k8.row.col.f32.tf32.tf32.f32 "
        "{%0,%1,%2,%3}, {%4,%5,%6,%7}, {%8,%9}, {%0,%1,%2,%3};"
        : "+f"(d[0]), "+f"(d[1]), "+f"(d[2]), "+f"(d[3])
        : "r"(a[0]), "r"(a[1]), "r"(a[2]), "r"(a[3]), "r"(b[0]), "r"(b[1]));
}

// ---------------- reductions ----------------
__device__ __forceinline__ float block_reduce_sum(float v, float* red) {
    int tid = threadIdx.x;
    red[tid] = v;
    __syncthreads();
    for (int s = 128; s > 0; s >>= 1) {
        if (tid < s) red[tid] += red[tid + s];
        __syncthreads();
    }
    float r = red[0];
    __syncthreads();
    return r;
}

// ---------------- spectral norm sigma ----------------
__global__ void sigma_kernel(const float* W, const float* u, int R, int C, int slot) {
    __shared__ float sv[1152];
    __shared__ float red[256];
    int tid = threadIdx.x;

    float ss = 0.f;
    for (int j = tid; j < C; j += 256) {
        float t = 0.f;
        for (int i = 0; i < R; i++) t += W[i * C + j] * u[i];
        sv[j] = t;
        ss += t * t;
    }
    __syncthreads();
    float nrm2 = block_reduce_sum(ss, red);
    float invn = 1.0f / (sqrtf(nrm2) + 1e-12f);

    float ss2 = 0.f;
    for (int i = tid; i < R; i += 256) {
        float s = 0.f;
        for (int j = 0; j < C; j++) s += W[i * C + j] * sv[j];
        s *= invn;
        ss2 += s * s;
    }
    float sig2 = block_reduce_sum(ss2, red);
    if (tid == 0) {
        float sigma = sig2 / (sqrtf(sig2) + 1e-12f);
        g_inv_sigma[slot] = 1.0f / sigma;
    }
}

// ---------------- scale / transpose weights ----------------
__global__ void scale_w(const float* src) {      // conv_w [cout][k], pre-round to tf32
    int idx = blockIdx.x * 256 + threadIdx.x;
    if (idx < 128 * 1152) g_ws[idx] = __uint_as_float(f2tf32(src[idx] * g_inv_sigma[0]));
}
__global__ void transpose_fcv(const float* src) {
    int idx = blockIdx.x * 256 + threadIdx.x;
    if (idx >= 256 * 512) return;
    int r = idx / 512, c = idx - r * 512;
    g_fcvT[c * 256 + r] = src[idx] * g_inv_sigma[1];
}
__global__ void transpose_fct(const float* src) {
    int idx = blockIdx.x * 256 + threadIdx.x;
    if (idx >= 256 * 128) return;
    int r = idx / 128, c = idx - r * 128;
    g_fctT[c * 256 + r] = src[idx] * g_inv_sigma[2];
}

// ---------------- init ----------------
__global__ void init_kernel() {
    int idx = blockIdx.x * 256 + threadIdx.x;
    if (idx < NN * DD) g_h[idx] = 0.f;
    if (idx < NN) g_deg[idx] = 1.0f;
}

// ---------------- degree + normalization ----------------
__global__ void deg_kernel(const int* __restrict__ ei) {
    int e = blockIdx.x * 256 + threadIdx.x;
    if (e < NE) atomicAdd(&g_deg[clampi(ei[NE + e], 0, NN - 1)], 1.0f);
}
__global__ void dis_kernel() {
    int i = blockIdx.x * 256 + threadIdx.x;
    if (i < NN) g_dis[i] = rsqrtf(g_deg[i]);
}

// ---------------- xw = topo @ gcn_w ----------------
__global__ void xw_kernel(const float* __restrict__ topo, const float* __restrict__ gw) {
    __shared__ float st[8 * 128];
    int n0 = blockIdx.x * 8;
    int tid = threadIdx.x;
#pragma unroll
    for (int i = 0; i < 8; i++) st[i * 128 + tid] = topo[(n0 + i) * 128 + tid];
    __syncthreads();
    float acc[8];
#pragma unroll
    for (int r = 0; r < 8; r++) acc[r] = 0.f;
    for (int k = 0; k < 128; k++) {
        float w = gw[k * 128 + tid];
#pragma unroll
        for (int r = 0; r < 8; r++) acc[r] += st[r * 128 + k] * w;
    }
#pragma unroll
    for (int r = 0; r < 8; r++) g_xw[(n0 + r) * 128 + tid] = acc[r];
}

// ---------------- edge scatter via red.v4 ----------------
__global__ void scatter_kernel(const int* __restrict__ ei) {
    int e = blockIdx.x * 8 + (threadIdx.x >> 5);
    if (e >= NE) return;
    int lane = threadIdx.x & 31;
    int src = clampi(ei[e], 0, NN - 1);
    int dst = clampi(ei[NE + e], 0, NN - 1);
    float nrm = g_dis[src] * g_dis[dst];
    float4 v = *(const float4*)&g_xw[src * 128 + lane * 4];
    asm volatile("red.global.add.v4.f32 [%0], {%1, %2, %3, %4};"
                 :: "l"(&g_h[dst * 128 + lane * 4]),
                    "f"(v.x * nrm), "f"(v.y * nrm), "f"(v.z * nrm), "f"(v.w * nrm)
                 : "memory");
}

// ---------------- topo pool ----------------
__global__ void topo_pool_kernel(const int* __restrict__ batch, const float* __restrict__ gb) {
    int b = blockIdx.x;
    int stripe = blockIdx.y;
    int c = threadIdx.x;

    int lo = 0, hi = NN;
    while (lo < hi) { int mid = (lo + hi) >> 1; if (batch[mid] < b) lo = mid + 1; else hi = mid; }
    int s = lo;
    lo = s; hi = NN;
    while (lo < hi) { int mid = (lo + hi) >> 1; if (batch[mid] < b + 1) lo = mid + 1; else hi = mid; }
    int e = lo;

    float bias = gb[c];
    float m = -INFINITY;
    for (int n = s + stripe; n < e; n += 4) {
        float d = g_dis[n];
        float val = g_h[n * 128 + c] + d * d * g_xw[n * 128 + c] + bias;
        val = (val >= 0.f) ? val : 0.2f * val;
        m = fmaxf(m, val);
    }
    g_topo_part[(b * 4 + stripe) * 128 + c] = m;
}

// ---------------- conv3x3: warp-MMA tf32 implicit GEMM + fused pool ----------------
// block: 128 pixels (M) x 128 cout (N); 8 warps in 4x2 (warp tile 32x64)
__global__ void __launch_bounds__(256)
conv_mma_kernel(const float* __restrict__ vis, const float* __restrict__ cb) {
    __shared__ __align__(16) float sAB[2 * KC * 136];  // sA[k][136], sB[k][136]; epilogue overlay [128][33]
    __shared__ int skoff[KTOT];
    __shared__ float sbias[DD];
    __shared__ unsigned char srowreg[128];

    float* sA = sAB;
    float* sB = sAB + KC * 136;

    int tid = threadIdx.x;
    int warp = tid >> 5, lane = tid & 31;
    int wm = warp & 3;        // 0..3 -> rows 32*wm
    int wn = warp >> 2;       // 0..1 -> cols 64*wn
    int gq = lane >> 2, tg = lane & 3;

    int img = blockIdx.x / MT;
    int mt = blockIdx.x - img * MT;
    int m0 = mt * 128;

    for (int k = tid; k < KTOT; k += 256) {
        int ci = k / 9, rem = k - ci * 9, ky = rem / 3, kx = rem - ky * 3;
        skoff[k] = ci * 4096 + ky * 64 + kx;
    }
    if (tid < 128) {
        sbias[tid] = cb[tid];
        int s = m0 + tid;
        unsigned char r = 4;
        if (s < MPI) {
            int yy = s / HOUT, xx = s - yy * HOUT;
            r = (unsigned char)(((yy >= 31) ? 2 : 0) + ((xx >= 31) ? 1 : 0));
        }
        srowreg[tid] = r;
    }

    // A gather setup
    int p = tid & 127;
    int kb = tid >> 7;   // 0/1
    int s = m0 + p;
    bool valid = (s < MPI);
    int y = valid ? (s / HOUT) : 0;
    int x = valid ? (s - y * HOUT) : 0;
    const float* base = vis + (size_t)img * 128 * 4096 + y * 64 + x;

    // B load setup: n = tid>>1, kk0 = (tid&1)*16
    int bn = tid >> 1;
    int bk0 = (tid & 1) * 16;

    float acc[2][8][4];
#pragma unroll
    for (int mi = 0; mi < 2; mi++)
#pragma unroll
        for (int ni = 0; ni < 8; ni++)
#pragma unroll
            for (int c = 0; c < 4; c++) acc[mi][ni][c] = 0.f;

    __syncthreads();

    for (int ch = 0; ch < NCHUNK; ch++) {
        int kg0 = ch * KC;
        // A: [KC][128 pixels]
#pragma unroll
        for (int i = 0; i < 16; i++) {
            int k = kb + 2 * i;
            float v = valid ? base[skoff[kg0 + k]] : 0.f;
            sA[k * 136 + p] = __uint_as_float(f2tf32(v));
        }
        // B: [KC][128 cout] (pre-rounded tf32)
#pragma unroll
        for (int j = 0; j < 4; j++) {
            float4 w = *(const float4*)&g_ws[bn * KTOT + kg0 + bk0 + j * 4];
            sB[(bk0 + j * 4 + 0) * 136 + bn] = w.x;
            sB[(bk0 + j * 4 + 1) * 136 + bn] = w.y;
            sB[(bk0 + j * 4 + 2) * 136 + bn] = w.z;
            sB[(bk0 + j * 4 + 3) * 136 + bn] = w.w;
        }
        __syncthreads();

#pragma unroll
        for (int ks = 0; ks < 4; ks++) {
            int k0 = ks * 8;
            uint32_t a[2][4], b[8][2];
#pragma unroll
            for (int mi = 0; mi < 2; mi++) {
                int rb = wm * 32 + mi * 16;
                a[mi][0] = __float_as_uint(sA[(k0 + tg) * 136 + rb + gq]);
                a[mi][1] = __float_as_uint(sA[(k0 + tg) * 136 + rb + gq + 8]);
                a[mi][2] = __float_as_uint(sA[(k0 + tg + 4) * 136 + rb + gq]);
                a[mi][3] = __float_as_uint(sA[(k0 + tg + 4) * 136 + rb + gq + 8]);
            }
#pragma unroll
            for (int ni = 0; ni < 8; ni++) {
                int nb = wn * 64 + ni * 8;
                b[ni][0] = __float_as_uint(sB[(k0 + tg) * 136 + nb + gq]);
                b[ni][1] = __float_as_uint(sB[(k0 + tg + 4) * 136 + nb + gq]);
            }
#pragma unroll
            for (int mi = 0; mi < 2; mi++)
#pragma unroll
                for (int ni = 0; ni < 8; ni++)
                    mma_tf32(acc[mi][ni], a[mi], b[ni]);
        }
        __syncthreads();
    }

    // ---------------- epilogue: 4 column passes of 32 cols ----------------
    float* sm = sAB;   // overlay [128][33]
    for (int q = 0; q < 4; q++) {
        if ((q >> 1) == wn) {
            int ni0 = (q & 1) * 4;
#pragma unroll
            for (int mi = 0; mi < 2; mi++) {
#pragma unroll
                for (int nj = 0; nj < 4; nj++) {
                    int ni = ni0 + nj;
                    int colg = wn * 64 + ni * 8 + 2 * tg;      // global col
                    int colp = (colg - q * 32);                // col within pass
                    int r0 = wm * 32 + mi * 16 + gq;
#pragma unroll
                    for (int cc = 0; cc < 2; cc++) {
                        float v0 = acc[mi][ni][cc] + sbias[colg + cc];
                        v0 = (v0 >= 0.f) ? v0 : 0.2f * v0;
                        float v2 = acc[mi][ni][2 + cc] + sbias[colg + cc];
                        v2 = (v2 >= 0.f) ? v2 : 0.2f * v2;
                        sm[r0 * 33 + colp + cc] = v0;
                        sm[(r0 + 8) * 33 + colp + cc] = v2;
                    }
                }
            }
        }
        __syncthreads();
        if (tid < 128) {
            int ccol = tid & 31;
            int myreg = tid >> 5;
            float mx = -INFINITY;
            for (int row = 0; row < 128; row++) {
                float v = sm[row * 33 + ccol];
                mx = (srowreg[row] == (unsigned char)myreg) ? fmaxf(mx, v) : mx;
            }
            g_partial[((img * MT + mt) * 4 + myreg) * 128 + q * 32 + ccol] = mx;
        }
        __syncthreads();
    }
}

// ---------------- reduce conv-tile partials -> g_pool_vis ----------------
__global__ void vis_reduce_kernel() {
    int img = blockIdx.x;
    int o = threadIdx.x;    // 512
    int r = o >> 7;
    int col = o & 127;
    float m = -INFINITY;
    for (int mt = 0; mt < MT; mt++)
        m = fmaxf(m, g_partial[((img * MT + mt) * 4 + r) * 128 + col]);
    g_pool_vis[img * 512 + col * 4 + r] = m;
}

// ---------------- vis score ----------------
__global__ void vis_score_kernel(const float* __restrict__ fcvb, float* __restrict__ out) {
    __shared__ float xs[512];
    int b = blockIdx.x, tid = threadIdx.x;
    for (int i = tid; i < 512; i += 256) xs[i] = g_pool_vis[b * 512 + i];
    __syncthreads();
    float acc = fcvb[tid];
    for (int j = 0; j < 512; j++) acc += xs[j] * g_fcvT[j * OUTD + tid];
    out[b * OUTD + tid] = acc;
}

// ---------------- topo score ----------------
__global__ void topo_score_kernel(const float* __restrict__ fctb, float* __restrict__ out) {
    __shared__ float xs[128];
    int b = blockIdx.x, tid = threadIdx.x;
    if (tid < 128) {
        float m = g_topo_part[(b * 4 + 0) * 128 + tid];
        m = fmaxf(m, g_topo_part[(b * 4 + 1) * 128 + tid]);
        m = fmaxf(m, g_topo_part[(b * 4 + 2) * 128 + tid]);
        m = fmaxf(m, g_topo_part[(b * 4 + 3) * 128 + tid]);
        xs[tid] = m;
    }
    __syncthreads();
    float acc = fctb[tid];
    for (int j = 0; j < 128; j++) acc += xs[j] * g_fctT[j * OUTD + tid];
    out[BBATCH * OUTD + b * OUTD + tid] = acc;
}

// ---------------- launch ----------------
extern "C" void kernel_launch(void* const* d_in, const int* in_sizes, int n_in,
                              void* d_out, int out_size) {
    const float* vis    = (const float*)d_in[0];
    const float* topo   = (const float*)d_in[1];
    const int*   ei     = (const int*)d_in[2];
    const int*   batch  = (const int*)d_in[3];
    const float* conv_w = (const float*)d_in[4];
    const float* conv_b = (const float*)d_in[5];
    const float* conv_u = (const float*)d_in[6];
    const float* fcv_w  = (const float*)d_in[7];
    const float* fcv_b  = (const float*)d_in[8];
    const float* fcv_u  = (const float*)d_in[9];
    const float* gcn_w  = (const float*)d_in[10];
    const float* gcn_b  = (const float*)d_in[11];
    const float* fct_w  = (const float*)d_in[12];
    const float* fct_b  = (const float*)d_in[13];
    const float* fct_u  = (const float*)d_in[14];
    float*       out    = (float*)d_out;

    sigma_kernel<<<1, 256>>>(conv_w, conv_u, 128, 1152, 0);
    sigma_kernel<<<1, 256>>>(fcv_w, fcv_u, 256, 512, 1);
    sigma_kernel<<<1, 256>>>(fct_w, fct_u, 256, 128, 2);

    scale_w      <<<(128 * 1152 + 255) / 256, 256>>>(conv_w);
    transpose_fcv<<<(256 * 512 + 255) / 256, 256>>>(fcv_w);
    transpose_fct<<<(256 * 128 + 255) / 256, 256>>>(fct_w);

    init_kernel<<<(NN * DD + 255) / 256, 256>>>();

    // vision head: warp-MMA tf32 implicit-GEMM conv + fused pool
    conv_mma_kernel<<<BBATCH * MT, 256>>>(vis, conv_b);
    vis_reduce_kernel<<<BBATCH, 512>>>();

    // topo head
    deg_kernel<<<(NE + 255) / 256, 256>>>(ei);
    dis_kernel<<<(NN + 255) / 256, 256>>>();
    xw_kernel<<<NN / 8, 128>>>(topo, gcn_w);
    scatter_kernel<<<NE / 8, 256>>>(ei);
    {
        dim3 g(BBATCH, 4);
        topo_pool_kernel<<<g, 128>>>(batch, gcn_b);
    }

    vis_score_kernel<<<BBATCH, 256>>>(fcv_b, out);
    topo_score_kernel<<<BBATCH, 256>>>(fct_b, out);
}

// round 8
// speedup vs baseline: 1.5049x; 1.3902x over previous
#include <cuda_runtime.h>
#include <math.h>
#include <stdint.h>

#define NN 20000
#define NE 640000
#define DD 128
#define OUTD 256
#define BBATCH 64
#define HOUT 62
#define MPI (HOUT*HOUT)   // 3844 pixels per image
#define MT 31             // M-tiles of 128 per image
#define KTOT 1152
#define KC 32             // K chunk
#define NCHUNK (KTOT/KC)  // 36

// ---------------- scratch ----------------
__device__ __align__(16) float g_inv_sigma[4];
__device__ __align__(16) float g_ws[DD * KTOT];        // conv weights [cout][k]/sigma, tf32-rounded
__device__ __align__(16) float g_fcvT[512 * OUTD];
__device__ __align__(16) float g_fctT[DD * OUTD];
__device__ __align__(16) float g_partial[BBATCH * MT * 4 * DD];
__device__ __align__(16) float g_pool_vis[BBATCH * DD * 4];
__device__ __align__(16) float g_topo_part[BBATCH * 4 * DD];
__device__ __align__(16) float g_deg[NN];
__device__ __align__(16) float g_dis[NN];
__device__ __align__(16) float g_xw[NN * DD];
__device__ __align__(16) float g_h[NN * DD];

__device__ __forceinline__ int clampi(int v, int lo, int hi) {
    return v < lo ? lo : (v > hi ? hi : v);
}
__device__ __forceinline__ uint32_t f2tf32(float f) {
    uint32_t u;
    asm("cvt.rna.tf32.f32 %0, %1;" : "=r"(u) : "f"(f));
    return u;
}
__device__ __forceinline__ void mma_tf32(float* d, const uint32_t* a, const uint32_t* b) {
    asm volatile(
        "mma.sync.aligned.m16n8k8.row.col.f32.tf32.tf32.f32 "
        "{%0,%1,%2,%3}, {%4,%5,%6,%7}, {%8,%9}, {%0,%1,%2,%3};"
        : "+f"(d[0]), "+f"(d[1]), "+f"(d[2]), "+f"(d[3])
        : "r"(a[0]), "r"(a[1]), "r"(a[2]), "r"(a[3]), "r"(b[0]), "r"(b[1]));
}

// ---------------- reductions ----------------
__device__ __forceinline__ float block_reduce_sum(float v, float* red) {
    int tid = threadIdx.x;
    red[tid] = v;
    __syncthreads();
    for (int s = 128; s > 0; s >>= 1) {
        if (tid < s) red[tid] += red[tid + s];
        __syncthreads();
    }
    float r = red[0];
    __syncthreads();
    return r;
}

// ---------------- spectral norm sigma ----------------
__global__ void sigma_kernel(const float* W, const float* u, int R, int C, int slot) {
    __shared__ float sv[1152];
    __shared__ float red[256];
    int tid = threadIdx.x;

    float ss = 0.f;
    for (int j = tid; j < C; j += 256) {
        float t = 0.f;
        for (int i = 0; i < R; i++) t += W[i * C + j] * u[i];
        sv[j] = t;
        ss += t * t;
    }
    __syncthreads();
    float nrm2 = block_reduce_sum(ss, red);
    float invn = 1.0f / (sqrtf(nrm2) + 1e-12f);

    float ss2 = 0.f;
    for (int i = tid; i < R; i += 256) {
        float s = 0.f;
        for (int j = 0; j < C; j++) s += W[i * C + j] * sv[j];
        s *= invn;
        ss2 += s * s;
    }
    float sig2 = block_reduce_sum(ss2, red);
    if (tid == 0) {
        float sigma = sig2 / (sqrtf(sig2) + 1e-12f);
        g_inv_sigma[slot] = 1.0f / sigma;
    }
}

// ---------------- scale / transpose weights ----------------
__global__ void scale_w(const float* src) {      // conv_w [cout][k], pre-round to tf32
    int idx = blockIdx.x * 256 + threadIdx.x;
    if (idx < 128 * 1152) g_ws[idx] = __uint_as_float(f2tf32(src[idx] * g_inv_sigma[0]));
}
__global__ void transpose_fcv(const float* src) {
    int idx = blockIdx.x * 256 + threadIdx.x;
    if (idx >= 256 * 512) return;
    int r = idx / 512, c = idx - r * 512;
    g_fcvT[c * 256 + r] = src[idx] * g_inv_sigma[1];
}
__global__ void transpose_fct(const float* src) {
    int idx = blockIdx.x * 256 + threadIdx.x;
    if (idx >= 256 * 128) return;
    int r = idx / 128, c = idx - r * 128;
    g_fctT[c * 256 + r] = src[idx] * g_inv_sigma[2];
}

// ---------------- init ----------------
__global__ void init_kernel() {
    int idx = blockIdx.x * 256 + threadIdx.x;
    if (idx < NN * DD) g_h[idx] = 0.f;
    if (idx < NN) g_deg[idx] = 1.0f;
}

// ---------------- degree + normalization ----------------
__global__ void deg_kernel(const int* __restrict__ ei) {
    int e = blockIdx.x * 256 + threadIdx.x;
    if (e < NE) atomicAdd(&g_deg[clampi(ei[NE + e], 0, NN - 1)], 1.0f);
}
__global__ void dis_kernel() {
    int i = blockIdx.x * 256 + threadIdx.x;
    if (i < NN) g_dis[i] = rsqrtf(g_deg[i]);
}

// ---------------- xw = topo @ gcn_w ----------------
__global__ void xw_kernel(const float* __restrict__ topo, const float* __restrict__ gw) {
    __shared__ float st[8 * 128];
    int n0 = blockIdx.x * 8;
    int tid = threadIdx.x;
#pragma unroll
    for (int i = 0; i < 8; i++) st[i * 128 + tid] = topo[(n0 + i) * 128 + tid];
    __syncthreads();
    float acc[8];
#pragma unroll
    for (int r = 0; r < 8; r++) acc[r] = 0.f;
    for (int k = 0; k < 128; k++) {
        float w = gw[k * 128 + tid];
#pragma unroll
        for (int r = 0; r < 8; r++) acc[r] += st[r * 128 + k] * w;
    }
#pragma unroll
    for (int r = 0; r < 8; r++) g_xw[(n0 + r) * 128 + tid] = acc[r];
}

// ---------------- edge scatter via red.v4 ----------------
__global__ void scatter_kernel(const int* __restrict__ ei) {
    int e = blockIdx.x * 8 + (threadIdx.x >> 5);
    if (e >= NE) return;
    int lane = threadIdx.x & 31;
    int src = clampi(ei[e], 0, NN - 1);
    int dst = clampi(ei[NE + e], 0, NN - 1);
    float nrm = g_dis[src] * g_dis[dst];
    float4 v = *(const float4*)&g_xw[src * 128 + lane * 4];
    asm volatile("red.global.add.v4.f32 [%0], {%1, %2, %3, %4};"
                 :: "l"(&g_h[dst * 128 + lane * 4]),
                    "f"(v.x * nrm), "f"(v.y * nrm), "f"(v.z * nrm), "f"(v.w * nrm)
                 : "memory");
}

// ---------------- topo pool ----------------
__global__ void topo_pool_kernel(const int* __restrict__ batch, const float* __restrict__ gb) {
    int b = blockIdx.x;
    int stripe = blockIdx.y;
    int c = threadIdx.x;

    int lo = 0, hi = NN;
    while (lo < hi) { int mid = (lo + hi) >> 1; if (batch[mid] < b) lo = mid + 1; else hi = mid; }
    int s = lo;
    lo = s; hi = NN;
    while (lo < hi) { int mid = (lo + hi) >> 1; if (batch[mid] < b + 1) lo = mid + 1; else hi = mid; }
    int e = lo;

    float bias = gb[c];
    float m = -INFINITY;
    for (int n = s + stripe; n < e; n += 4) {
        float d = g_dis[n];
        float val = g_h[n * 128 + c] + d * d * g_xw[n * 128 + c] + bias;
        val = (val >= 0.f) ? val : 0.2f * val;
        m = fmaxf(m, val);
    }
    g_topo_part[(b * 4 + stripe) * 128 + c] = m;
}

// ---------------- conv3x3: warp-MMA tf32 implicit GEMM, double-buffered ----------------
// block: 128 pixels (M) x 128 cout (N); 8 warps in 4x2 (warp tile 32x64)
__global__ void __launch_bounds__(256)
conv_mma_kernel(const float* __restrict__ vis, const float* __restrict__ cb) {
    __shared__ __align__(16) float sbuf[2][2 * KC * 136];  // [buf][ sA(KC*136) | sB(KC*136) ]
    __shared__ int skoff[KTOT];
    __shared__ float sbias[DD];
    __shared__ unsigned char srowreg[128];

    int tid = threadIdx.x;
    int warp = tid >> 5, lane = tid & 31;
    int wm = warp & 3;        // rows 32*wm
    int wn = warp >> 2;       // cols 64*wn
    int gq = lane >> 2, tg = lane & 3;

    int img = blockIdx.x / MT;
    int mt = blockIdx.x - img * MT;
    int m0 = mt * 128;

    for (int k = tid; k < KTOT; k += 256) {
        int ci = k / 9, rem = k - ci * 9, ky = rem / 3, kx = rem - ky * 3;
        skoff[k] = ci * 4096 + ky * 64 + kx;
    }
    if (tid < 128) {
        sbias[tid] = cb[tid];
        int s = m0 + tid;
        unsigned char r = 4;
        if (s < MPI) {
            int yy = s / HOUT, xx = s - yy * HOUT;
            r = (unsigned char)(((yy >= 31) ? 2 : 0) + ((xx >= 31) ? 1 : 0));
        }
        srowreg[tid] = r;
    }

    // A gather setup
    int p = tid & 127;
    int kb = tid >> 7;   // 0/1
    int s = m0 + p;
    bool valid = (s < MPI);
    int y = valid ? (s / HOUT) : 0;
    int x = valid ? (s - y * HOUT) : 0;
    const float* base = vis + (size_t)img * 128 * 4096 + y * 64 + x;

    // B load setup
    int bn = tid >> 1;
    int bk0 = (tid & 1) * 16;
    const float* wrow = &g_ws[bn * KTOT + bk0];

    float acc[2][8][4];
#pragma unroll
    for (int mi = 0; mi < 2; mi++)
#pragma unroll
        for (int ni = 0; ni < 8; ni++)
#pragma unroll
            for (int c = 0; c < 4; c++) acc[mi][ni][c] = 0.f;

    float pa[16];
    float4 pb[4];
    __syncthreads();   // skoff ready

    // prologue: chunk 0 -> regs -> buf0
#pragma unroll
    for (int i = 0; i < 16; i++) {
        int k = kb + 2 * i;
        pa[i] = valid ? base[skoff[k]] : 0.f;
    }
#pragma unroll
    for (int j = 0; j < 4; j++) pb[j] = *(const float4*)(wrow + j * 4);
    {
        float* sA = sbuf[0];
        float* sB = sbuf[0] + KC * 136;
#pragma unroll
        for (int i = 0; i < 16; i++) {
            int k = kb + 2 * i;
            sA[k * 136 + p] = __uint_as_float(f2tf32(pa[i]));
        }
#pragma unroll
        for (int j = 0; j < 4; j++) {
            sB[(bk0 + j * 4 + 0) * 136 + bn] = pb[j].x;
            sB[(bk0 + j * 4 + 1) * 136 + bn] = pb[j].y;
            sB[(bk0 + j * 4 + 2) * 136 + bn] = pb[j].z;
            sB[(bk0 + j * 4 + 3) * 136 + bn] = pb[j].w;
        }
    }

    for (int ch = 0; ch < NCHUNK; ch++) {
        __syncthreads();                 // buf[ch&1] ready for all
        // prefetch next chunk into regs (overlaps MMA below)
        if (ch + 1 < NCHUNK) {
            int kg0 = (ch + 1) * KC;
#pragma unroll
            for (int i = 0; i < 16; i++) {
                int k = kb + 2 * i;
                pa[i] = valid ? base[skoff[kg0 + k]] : 0.f;
            }
#pragma unroll
            for (int j = 0; j < 4; j++) pb[j] = *(const float4*)(wrow + kg0 + j * 4);
        }

        float* sA = sbuf[ch & 1];
        float* sB = sbuf[ch & 1] + KC * 136;
#pragma unroll
        for (int ks = 0; ks < 4; ks++) {
            int k0 = ks * 8;
            uint32_t a[2][4], b[8][2];
#pragma unroll
            for (int mi = 0; mi < 2; mi++) {
                int rb = wm * 32 + mi * 16;
                a[mi][0] = __float_as_uint(sA[(k0 + tg) * 136 + rb + gq]);
                a[mi][1] = __float_as_uint(sA[(k0 + tg) * 136 + rb + gq + 8]);
                a[mi][2] = __float_as_uint(sA[(k0 + tg + 4) * 136 + rb + gq]);
                a[mi][3] = __float_as_uint(sA[(k0 + tg + 4) * 136 + rb + gq + 8]);
            }
#pragma unroll
            for (int ni = 0; ni < 8; ni++) {
                int nb = wn * 64 + ni * 8;
                b[ni][0] = __float_as_uint(sB[(k0 + tg) * 136 + nb + gq]);
                b[ni][1] = __float_as_uint(sB[(k0 + tg + 4) * 136 + nb + gq]);
            }
#pragma unroll
            for (int mi = 0; mi < 2; mi++)
#pragma unroll
                for (int ni = 0; ni < 8; ni++)
                    mma_tf32(acc[mi][ni], a[mi], b[ni]);
        }

        // store prefetched regs into the other buffer (safe: nobody reads it now)
        if (ch + 1 < NCHUNK) {
            float* dA = sbuf[(ch + 1) & 1];
            float* dB = dA + KC * 136;
#pragma unroll
            for (int i = 0; i < 16; i++) {
                int k = kb + 2 * i;
                dA[k * 136 + p] = __uint_as_float(f2tf32(pa[i]));
            }
#pragma unroll
            for (int j = 0; j < 4; j++) {
                dB[(bk0 + j * 4 + 0) * 136 + bn] = pb[j].x;
                dB[(bk0 + j * 4 + 1) * 136 + bn] = pb[j].y;
                dB[(bk0 + j * 4 + 2) * 136 + bn] = pb[j].z;
                dB[(bk0 + j * 4 + 3) * 136 + bn] = pb[j].w;
            }
        }
    }
    __syncthreads();   // all MMAs done before epilogue overlays sbuf[0]

    // ---------------- epilogue: 4 column passes of 32 cols ----------------
    float* sm = sbuf[0];   // overlay [128][33]
    for (int q = 0; q < 4; q++) {
        if ((q >> 1) == wn) {
            int ni0 = (q & 1) * 4;
#pragma unroll
            for (int mi = 0; mi < 2; mi++) {
#pragma unroll
                for (int nj = 0; nj < 4; nj++) {
                    int ni = ni0 + nj;
                    int colg = wn * 64 + ni * 8 + 2 * tg;
                    int colp = (colg - q * 32);
                    int r0 = wm * 32 + mi * 16 + gq;
#pragma unroll
                    for (int cc = 0; cc < 2; cc++) {
                        float v0 = acc[mi][ni][cc] + sbias[colg + cc];
                        v0 = (v0 >= 0.f) ? v0 : 0.2f * v0;
                        float v2 = acc[mi][ni][2 + cc] + sbias[colg + cc];
                        v2 = (v2 >= 0.f) ? v2 : 0.2f * v2;
                        sm[r0 * 33 + colp + cc] = v0;
                        sm[(r0 + 8) * 33 + colp + cc] = v2;
                    }
                }
            }
        }
        __syncthreads();
        if (tid < 128) {
            int ccol = tid & 31;
            int myreg = tid >> 5;
            float mx = -INFINITY;
            for (int row = 0; row < 128; row++) {
                float v = sm[row * 33 + ccol];
                mx = (srowreg[row] == (unsigned char)myreg) ? fmaxf(mx, v) : mx;
            }
            g_partial[((img * MT + mt) * 4 + myreg) * 128 + q * 32 + ccol] = mx;
        }
        __syncthreads();
    }
}

// ---------------- reduce conv-tile partials -> g_pool_vis ----------------
__global__ void vis_reduce_kernel() {
    int img = blockIdx.x;
    int o = threadIdx.x;    // 512
    int r = o >> 7;
    int col = o & 127;
    float m = -INFINITY;
    for (int mt = 0; mt < MT; mt++)
        m = fmaxf(m, g_partial[((img * MT + mt) * 4 + r) * 128 + col]);
    g_pool_vis[img * 512 + col * 4 + r] = m;
}

// ---------------- vis score ----------------
__global__ void vis_score_kernel(const float* __restrict__ fcvb, float* __restrict__ out) {
    __shared__ float xs[512];
    int b = blockIdx.x, tid = threadIdx.x;
    for (int i = tid; i < 512; i += 256) xs[i] = g_pool_vis[b * 512 + i];
    __syncthreads();
    float acc = fcvb[tid];
    for (int j = 0; j < 512; j++) acc += xs[j] * g_fcvT[j * OUTD + tid];
    out[b * OUTD + tid] = acc;
}

// ---------------- topo score ----------------
__global__ void topo_score_kernel(const float* __restrict__ fctb, float* __restrict__ out) {
    __shared__ float xs[128];
    int b = blockIdx.x, tid = threadIdx.x;
    if (tid < 128) {
        float m = g_topo_part[(b * 4 + 0) * 128 + tid];
        m = fmaxf(m, g_topo_part[(b * 4 + 1) * 128 + tid]);
        m = fmaxf(m, g_topo_part[(b * 4 + 2) * 128 + tid]);
        m = fmaxf(m, g_topo_part[(b * 4 + 3) * 128 + tid]);
        xs[tid] = m;
    }
    __syncthreads();
    float acc = fctb[tid];
    for (int j = 0; j < 128; j++) acc += xs[j] * g_fctT[j * OUTD + tid];
    out[BBATCH * OUTD + b * OUTD + tid] = acc;
}

// ---------------- launch (conv placed 4th: ncu -s5-c1 lands there) ----------------
extern "C" void kernel_launch(void* const* d_in, const int* in_sizes, int n_in,
                              void* d_out, int out_size) {
    const float* vis    = (const float*)d_in[0];
    const float* topo   = (const float*)d_in[1];
    const int*   ei     = (const int*)d_in[2];
    const int*   batch  = (const int*)d_in[3];
    const float* conv_w = (const float*)d_in[4];
    const float* conv_b = (const float*)d_in[5];
    const float* conv_u = (const float*)d_in[6];
    const float* fcv_w  = (const float*)d_in[7];
    const float* fcv_b  = (const float*)d_in[8];
    const float* fcv_u  = (const float*)d_in[9];
    const float* gcn_w  = (const float*)d_in[10];
    const float* gcn_b  = (const float*)d_in[11];
    const float* fct_w  = (const float*)d_in[12];
    const float* fct_b  = (const float*)d_in[13];
    const float* fct_u  = (const float*)d_in[14];
    float*       out    = (float*)d_out;

    // 1..3
    sigma_kernel<<<1, 256>>>(conv_w, conv_u, 128, 1152, 0);
    scale_w<<<(128 * 1152 + 255) / 256, 256>>>(conv_w);
    init_kernel<<<(NN * DD + 255) / 256, 256>>>();
    // 4: conv (profiled slot)
    conv_mma_kernel<<<BBATCH * MT, 256>>>(vis, conv_b);

    // topo head
    deg_kernel<<<(NE + 255) / 256, 256>>>(ei);
    dis_kernel<<<(NN + 255) / 256, 256>>>();
    xw_kernel<<<NN / 8, 128>>>(topo, gcn_w);
    scatter_kernel<<<NE / 8, 256>>>(ei);

    // remaining weight prep
    sigma_kernel<<<1, 256>>>(fcv_w, fcv_u, 256, 512, 1);
    sigma_kernel<<<1, 256>>>(fct_w, fct_u, 256, 128, 2);
    transpose_fcv<<<(256 * 512 + 255) / 256, 256>>>(fcv_w);
    transpose_fct<<<(256 * 128 + 255) / 256, 256>>>(fct_w);

    vis_reduce_kernel<<<BBATCH, 512>>>();
    {
        dim3 g(BBATCH, 4);
        topo_pool_kernel<<<g, 128>>>(batch, gcn_b);
    }

    vis_score_kernel<<<BBATCH, 256>>>(fcv_b, out);
    topo_score_kernel<<<BBATCH, 256>>>(fct_b, out);
}